// round 13
// baseline (speedup 1.0000x reference)
#include <cuda_runtime.h>
#include <cuda_bf16.h>
#include <stdint.h>
#include <math.h>

#define NN 100000
#define D1 128
#define D2 64
#define EMAX 4000000
#define SCAN_BLK 1024
#define MAXNB 128
#define NCHUNKS 4

typedef unsigned long long ull;

// ---------------- scratch (static __device__ — no runtime allocation) ----------------
__device__ float  g_dis[NN];
__device__ float2 g_dis2[NN];
__device__ int    g_deg[NN];
__device__ int    g_rowstart[NN];
__device__ int    g_cursor[NN];
__device__ int    g_csr[EMAX];
__device__ int    g_blocksum[MAXNB];
__device__ int    g_blockoff[MAXNB];
__device__ float  g_H1[(size_t)NN * D1];
__device__ float  g_A1[(size_t)NN * D1];
__device__ float  g_H2[(size_t)NN * D2];
__device__ float  g_A2[(size_t)NN * D2];
__device__ int    g_is64;
// W in mma-fragment order: per (col, kstep, tg) one uint4 {hi_b0, hi_b1, lo_b0, lo_b1}
__device__ uint32_t g_Wf1[128 * 8 * 4 * 4];   // 64KB
__device__ uint32_t g_Wf2[64 * 8 * 4 * 4];    // 32KB

// ---------------- f32x2 helpers (gathers) ----------------
__device__ __forceinline__ ull pack2(float lo, float hi) {
    ull r; asm("mov.b64 %0, {%1,%2};" : "=l"(r) : "f"(lo), "f"(hi)); return r;
}
__device__ __forceinline__ float2 unpack2(ull u) {
    float2 f; asm("mov.b64 {%0,%1}, %2;" : "=f"(f.x), "=f"(f.y) : "l"(u)); return f;
}
__device__ __forceinline__ void ffma2(ull& d, ull a, ull b, ull c) {
    asm("fma.rn.f32x2 %0, %1, %2, %3;" : "=l"(d) : "l"(a), "l"(b), "l"(c));
}
__device__ __forceinline__ void fmul2(ull& d, ull a, ull b) {
    asm("mul.rn.f32x2 %0, %1, %2;" : "=l"(d) : "l"(a), "l"(b));
}

__device__ __forceinline__ int load_idx(const void* ei, long long pos, int is64) {
    return is64 ? (int)((const long long*)ei)[pos] : ((const int*)ei)[pos];
}

__device__ __forceinline__ uint32_t pkb(__nv_bfloat16 a, __nv_bfloat16 b) {
    return (uint32_t)__bfloat16_as_ushort(a) | ((uint32_t)__bfloat16_as_ushort(b) << 16);
}

// split float2 -> bf16x2 hi word + bf16x2 lo word (residual)
__device__ __forceinline__ void split2(float2 v, uint32_t& h, uint32_t& l) {
    uint32_t hw;
    asm("cvt.rn.bf16x2.f32 %0, %1, %2;" : "=r"(hw) : "f"(v.y), "f"(v.x));
    const float hx = __uint_as_float(hw << 16);
    const float hy = __uint_as_float(hw & 0xffff0000u);
    const float lx = v.x - hx;
    const float ly = v.y - hy;
    uint32_t lw;
    asm("cvt.rn.bf16x2.f32 %0, %1, %2;" : "=r"(lw) : "f"(ly), "f"(lx));
    h = hw; l = lw;
}

__device__ __forceinline__ void mma16816(float* c, const uint32_t* a, uint32_t b0, uint32_t b1) {
    asm volatile(
        "mma.sync.aligned.m16n8k16.row.col.f32.bf16.bf16.f32 "
        "{%0,%1,%2,%3}, {%4,%5,%6,%7}, {%8,%9}, {%0,%1,%2,%3};"
        : "+f"(c[0]), "+f"(c[1]), "+f"(c[2]), "+f"(c[3])
        : "r"(a[0]), "r"(a[1]), "r"(a[2]), "r"(a[3]), "r"(b0), "r"(b1));
}

// ---------------- setup / CSR build ----------------
__global__ void setup_kernel(const unsigned int* ei, int n) {
    int i = blockIdx.x * blockDim.x + threadIdx.x;
    if (i < n) g_deg[i] = 0;
    if (blockIdx.x == 0) {
        __shared__ int any;
        if (threadIdx.x == 0) any = 0;
        __syncthreads();
        int local = 0;
        for (int j = threadIdx.x; j < 2048; j += blockDim.x)
            if (ei[2 * j + 1] != 0u) local = 1;
        if (local) any = 1;
        __syncthreads();
        if (threadIdx.x == 0) g_is64 = (any == 0) ? 1 : 0;
    }
}

__global__ void count_kernel(const void* __restrict__ ei, long long E) {
    long long e = (long long)blockIdx.x * blockDim.x + threadIdx.x;
    if (e >= E) return;
    int dst = load_idx(ei, E + e, g_is64);
    atomicAdd(&g_deg[dst], 1);
}

__global__ void scanA_kernel(int n) {
    __shared__ int s[SCAN_BLK];
    int i = blockIdx.x * SCAN_BLK + threadIdx.x;
    s[threadIdx.x] = (i < n) ? g_deg[i] : 0;
    __syncthreads();
    for (int off = SCAN_BLK / 2; off > 0; off >>= 1) {
        if (threadIdx.x < off) s[threadIdx.x] += s[threadIdx.x + off];
        __syncthreads();
    }
    if (threadIdx.x == 0) g_blocksum[blockIdx.x] = s[0];
}

__global__ void scanB_kernel(int nb) {
    __shared__ int s[MAXNB];
    int v = (threadIdx.x < nb) ? g_blocksum[threadIdx.x] : 0;
    s[threadIdx.x] = v;
    __syncthreads();
    for (int off = 1; off < MAXNB; off <<= 1) {
        int t = (threadIdx.x >= off) ? s[threadIdx.x - off] : 0;
        __syncthreads();
        s[threadIdx.x] += t;
        __syncthreads();
    }
    if (threadIdx.x < nb) g_blockoff[threadIdx.x] = s[threadIdx.x] - v;
}

__global__ void scanC_kernel(int n) {
    __shared__ int s[SCAN_BLK];
    int i = blockIdx.x * SCAN_BLK + threadIdx.x;
    int v = (i < n) ? g_deg[i] : 0;
    s[threadIdx.x] = v;
    __syncthreads();
    for (int off = 1; off < SCAN_BLK; off <<= 1) {
        int t = (threadIdx.x >= off) ? s[threadIdx.x - off] : 0;
        __syncthreads();
        s[threadIdx.x] += t;
        __syncthreads();
    }
    if (i < n) {
        int excl = s[threadIdx.x] - v + g_blockoff[blockIdx.x];
        g_rowstart[i] = excl;
        g_cursor[i] = excl;
        float d = rsqrtf((float)(v + 1));
        g_dis[i] = d;
        g_dis2[i] = make_float2(d, d);
    }
}

__global__ void fill_kernel(const void* __restrict__ ei, long long E) {
    long long e = (long long)blockIdx.x * blockDim.x + threadIdx.x;
    if (e >= E) return;
    const int is64 = g_is64;
    int src = load_idx(ei, e, is64);
    int dst = load_idx(ei, E + e, is64);
    int pos = atomicAdd(&g_cursor[dst], 1);
    g_csr[pos] = src;
}

// ---------------- weight prep: fragment-order bf16 hi/lo pack ----------------
__global__ void prep_w_kernel(const float* __restrict__ W1, const float* __restrict__ W2) {
    const int idx = blockIdx.x * blockDim.x + threadIdx.x;
    if (idx < 128 * 64) {
        const int c = idx >> 6, w = idx & 63;
        const int k = w * 2;
        const float x0 = W1[k * 128 + c], x1 = W1[(k + 1) * 128 + c];
        const __nv_bfloat16 h0 = __float2bfloat16_rn(x0), h1 = __float2bfloat16_rn(x1);
        const uint32_t hw = pkb(h0, h1);
        const uint32_t lw = pkb(__float2bfloat16_rn(x0 - __bfloat162float(h0)),
                                __float2bfloat16_rn(x1 - __bfloat162float(h1)));
        const int ks = w >> 3, wi = w & 7, tg = wi & 3, slot = wi >> 2;
        const int frag = (c * 8 + ks) * 4 + tg;
        g_Wf1[frag * 4 + slot] = hw;
        g_Wf1[frag * 4 + 2 + slot] = lw;
    }
    if (idx < 64 * 64) {
        const int c = idx >> 6, w = idx & 63;
        const int k = w * 2;
        const float x0 = W2[k * 64 + c], x1 = W2[(k + 1) * 64 + c];
        const __nv_bfloat16 h0 = __float2bfloat16_rn(x0), h1 = __float2bfloat16_rn(x1);
        const uint32_t hw = pkb(h0, h1);
        const uint32_t lw = pkb(__float2bfloat16_rn(x0 - __bfloat162float(h0)),
                                __float2bfloat16_rn(x1 - __bfloat162float(h1)));
        const int ks = w >> 3, wi = w & 7, tg = wi & 3, slot = wi >> 2;
        const int frag = (c * 8 + ks) * 4 + tg;
        g_Wf2[frag * 4 + slot] = hw;
        g_Wf2[frag * 4 + 2 + slot] = lw;
    }
}

// ---------------- HMMA GEMM: H = X@W, bf16 hi/lo split, fp32 accum -----------------
// X/H pointers may be pre-offset by chunk; n is the row count for this chunk.
template <int OUT, bool RELU_IN>
__global__ void __launch_bounds__(256)
mma_gemm_kernel(const float* __restrict__ X, const uint32_t* __restrict__ Wf,
                const float* __restrict__ bin, float* __restrict__ H, int n) {
    __shared__ uint4 bs[2048];                 // 64 cols x 8 ks x 4 tg = 32KB

    const int tid = threadIdx.x;
    const int lane = tid & 31;
    const int wid = tid >> 5;
    const int wr = wid >> 1;
    const int wc = wid & 1;
    const int g = lane >> 2;
    const int tg = lane & 3;
    const int row0 = blockIdx.x * 128;
    const int cb = blockIdx.y * 64;

    {
        const uint4* src = (const uint4*)Wf + cb * 32;
        #pragma unroll
        for (int i = tid; i < 2048; i += 256) bs[i] = src[i];
    }
    __syncthreads();

    float acc[2][4][4];
    #pragma unroll
    for (int mt = 0; mt < 2; ++mt)
        #pragma unroll
        for (int nt = 0; nt < 4; ++nt)
            #pragma unroll
            for (int q = 0; q < 4; ++q) acc[mt][nt][q] = 0.f;

    const int rbase = row0 + wr * 32;

    auto ld2 = [&](int r, int k) -> float2 {
        if (r >= n) return make_float2(0.f, 0.f);
        float2 v = *(const float2*)&X[(size_t)r * 128 + k];
        if (RELU_IN) {
            const float2 b = *(const float2*)&bin[k];
            v.x = fmaxf(v.x + b.x, 0.f);
            v.y = fmaxf(v.y + b.y, 0.f);
        }
        return v;
    };

    #pragma unroll
    for (int ks = 0; ks < 8; ++ks) {
        uint32_t ah[2][4], al[2][4];
        const int k0 = ks * 16 + tg * 2;
        #pragma unroll
        for (int mt = 0; mt < 2; ++mt) {
            const int r0 = rbase + mt * 16 + g;
            const int r1 = r0 + 8;
            split2(ld2(r0, k0),     ah[mt][0], al[mt][0]);
            split2(ld2(r1, k0),     ah[mt][1], al[mt][1]);
            split2(ld2(r0, k0 + 8), ah[mt][2], al[mt][2]);
            split2(ld2(r1, k0 + 8), ah[mt][3], al[mt][3]);
        }
        uint32_t bh0[4], bh1[4], bl0[4], bl1[4];
        #pragma unroll
        for (int nt = 0; nt < 4; ++nt) {
            const int cl = wc * 32 + nt * 8 + g;
            const uint4 b = bs[(cl * 8 + ks) * 4 + tg];
            bh0[nt] = b.x; bh1[nt] = b.y; bl0[nt] = b.z; bl1[nt] = b.w;
        }
        #pragma unroll
        for (int mt = 0; mt < 2; ++mt)
            #pragma unroll
            for (int nt = 0; nt < 4; ++nt) {
                mma16816(acc[mt][nt], ah[mt], bh0[nt], bh1[nt]);
                mma16816(acc[mt][nt], ah[mt], bl0[nt], bl1[nt]);
                mma16816(acc[mt][nt], al[mt], bh0[nt], bh1[nt]);
            }
    }

    #pragma unroll
    for (int mt = 0; mt < 2; ++mt) {
        const int r0 = rbase + mt * 16 + g;
        const int r1 = r0 + 8;
        #pragma unroll
        for (int nt = 0; nt < 4; ++nt) {
            const int c0 = cb + wc * 32 + nt * 8 + tg * 2;
            if (r0 < n)
                *(float2*)&H[(size_t)r0 * OUT + c0] = make_float2(acc[mt][nt][0], acc[mt][nt][1]);
            if (r1 < n)
                *(float2*)&H[(size_t)r1 * OUT + c0] = make_float2(acc[mt][nt][2], acc[mt][nt][3]);
        }
    }
}

// -------- gather chunk: nodes [node0, node1): A[d] = dis[d]*(dis[d]*H[d] + sum dis[s]*H[s]) --
template <int D>
__global__ void gather_kernel(const float* __restrict__ H, float* __restrict__ A,
                              int node0, int node1) {
    constexpr int LPN = D / 4;
    const long long gt = (long long)blockIdx.x * blockDim.x + threadIdx.x;
    const int node = node0 + (int)(gt / LPN);
    const int l = (int)(gt % LPN);
    if (node >= node1) return;

    const float4* __restrict__ h4 = (const float4*)H;
    const ull* __restrict__ dis2 = (const ull*)g_dis2;
    const size_t col = (size_t)node * LPN + l;
    const ull dd = __ldg(&dis2[node]);

    float4 sv = h4[col];
    ull acc0, acc1;
    fmul2(acc0, pack2(sv.x, sv.y), dd);
    fmul2(acc1, pack2(sv.z, sv.w), dd);

    const int beg = g_rowstart[node];
    const int cnt = g_deg[node];

    #pragma unroll 4
    for (int j = 0; j < cnt; ++j) {
        const int src = __ldg(&g_csr[beg + j]);
        const ull ss = __ldg(&dis2[src]);
        const float4 v = h4[(size_t)src * LPN + l];
        ffma2(acc0, pack2(v.x, v.y), ss, acc0);
        ffma2(acc1, pack2(v.z, v.w), ss, acc1);
    }

    fmul2(acc0, acc0, dd);
    fmul2(acc1, acc1, dd);
    const float2 a = unpack2(acc0);
    const float2 b = unpack2(acc1);
    ((float4*)A)[col] = make_float4(a.x, a.y, b.x, b.y);
}

// ---------------- final chunk: out = softmax(relu(A2+b2) @ Wf + bf) ----------------
__global__ void final_kernel(const float* __restrict__ A2, const float* __restrict__ b2,
                             const float* __restrict__ Wf, const float* __restrict__ bf,
                             float* __restrict__ out, int node0, int node1) {
    __shared__ float Wfs[64 * 10];
    __shared__ float bfs[10];
    __shared__ float b2s[64];
    for (int i = threadIdx.x; i < 640; i += blockDim.x) Wfs[i] = Wf[i];
    if (threadIdx.x < 10) bfs[threadIdx.x] = bf[threadIdx.x];
    if (threadIdx.x < 64) b2s[threadIdx.x] = b2[threadIdx.x];
    __syncthreads();

    const int i = node0 + blockIdx.x * blockDim.x + threadIdx.x;
    if (i >= node1) return;

    float acc[10];
    #pragma unroll
    for (int c = 0; c < 10; ++c) acc[c] = bfs[c];

    #pragma unroll
    for (int kk = 0; kk < 64; kk += 4) {
        float4 v = *(const float4*)&A2[(size_t)i * 64 + kk];
        v.x = fmaxf(v.x + b2s[kk + 0], 0.f);
        v.y = fmaxf(v.y + b2s[kk + 1], 0.f);
        v.z = fmaxf(v.z + b2s[kk + 2], 0.f);
        v.w = fmaxf(v.w + b2s[kk + 3], 0.f);
        #pragma unroll
        for (int c = 0; c < 10; ++c) {
            acc[c] = fmaf(v.x, Wfs[(kk + 0) * 10 + c], acc[c]);
            acc[c] = fmaf(v.y, Wfs[(kk + 1) * 10 + c], acc[c]);
            acc[c] = fmaf(v.z, Wfs[(kk + 2) * 10 + c], acc[c]);
            acc[c] = fmaf(v.w, Wfs[(kk + 3) * 10 + c], acc[c]);
        }
    }

    float m = acc[0];
    #pragma unroll
    for (int c = 1; c < 10; ++c) m = fmaxf(m, acc[c]);
    float s = 0.f;
    float ex[10];
    #pragma unroll
    for (int c = 0; c < 10; ++c) { ex[c] = expf(acc[c] - m); s += ex[c]; }
    const float inv = 1.0f / s;
    #pragma unroll
    for (int c = 0; c < 10; ++c) out[(size_t)i * 10 + c] = ex[c] * inv;
}

// ---------------- launch ----------------
extern "C" void kernel_launch(void* const* d_in, const int* in_sizes, int n_in,
                              void* d_out, int out_size) {
    const float* x  = (const float*)d_in[0];
    const void*  ei = d_in[1];
    const float* W1 = (const float*)d_in[2];
    const float* b1 = (const float*)d_in[3];
    const float* W2 = (const float*)d_in[4];
    const float* b2 = (const float*)d_in[5];
    const float* Wf = (const float*)d_in[6];
    const float* bf = (const float*)d_in[7];
    float* out = (float*)d_out;

    const long long E = (long long)in_sizes[1] / 2;
    const int n = in_sizes[0] / D1;
    const int nb = (n + SCAN_BLK - 1) / SCAN_BLK;

    float *H1, *A1, *H2, *A2;
    cudaGetSymbolAddress((void**)&H1, g_H1);
    cudaGetSymbolAddress((void**)&A1, g_A1);
    cudaGetSymbolAddress((void**)&H2, g_H2);
    cudaGetSymbolAddress((void**)&A2, g_A2);
    uint32_t *Wf1, *Wf2;
    cudaGetSymbolAddress((void**)&Wf1, g_Wf1);
    cudaGetSymbolAddress((void**)&Wf2, g_Wf2);

    static cudaStream_t s1 = nullptr, s2 = nullptr;
    static cudaEvent_t evFork = nullptr, evJoin = nullptr, evJoin2 = nullptr;
    static cudaEvent_t evG1[NCHUNKS], evM2[NCHUNKS], evG2[NCHUNKS];
    if (!s1) {
        cudaStreamCreateWithFlags(&s1, cudaStreamNonBlocking);
        cudaStreamCreateWithFlags(&s2, cudaStreamNonBlocking);
        cudaEventCreateWithFlags(&evFork, cudaEventDisableTiming);
        cudaEventCreateWithFlags(&evJoin, cudaEventDisableTiming);
        cudaEventCreateWithFlags(&evJoin2, cudaEventDisableTiming);
        for (int c = 0; c < NCHUNKS; ++c) {
            cudaEventCreateWithFlags(&evG1[c], cudaEventDisableTiming);
            cudaEventCreateWithFlags(&evM2[c], cudaEventDisableTiming);
            cudaEventCreateWithFlags(&evG2[c], cudaEventDisableTiming);
        }
    }

    const int rowb = (n + 127) / 128;
    // chunk size in GEMM blocks (128 rows each)
    const int cblocks = (rowb + NCHUNKS - 1) / NCHUNKS;
    const int crows = cblocks * 128;

    // main: prep(0) ... gemm1 lands at submission index 3 (ncu capture slot)
    prep_w_kernel<<<32, 256>>>(W1, W2);
    cudaEventRecord(evFork, 0);
    cudaStreamWaitEvent(s1, evFork, 0);
    setup_kernel<<<(n + 255) / 256, 256, 0, s1>>>((const unsigned int*)ei, n);
    if (E > 0) count_kernel<<<(int)((E + 255) / 256), 256, 0, s1>>>(ei, E);
    mma_gemm_kernel<128, false><<<dim3(rowb, 2), 256>>>(x, Wf1, nullptr, H1, n);
    scanA_kernel<<<nb, SCAN_BLK, 0, s1>>>(n);
    scanB_kernel<<<1, MAXNB, 0, s1>>>(nb);
    scanC_kernel<<<nb, SCAN_BLK, 0, s1>>>(n);
    if (E > 0) fill_kernel<<<(int)((E + 255) / 256), 256, 0, s1>>>(ei, E);
    cudaEventRecord(evJoin, s1);

    // join: gather1 needs gemm1 (main) + CSR (side)
    cudaStreamWaitEvent(0, evJoin, 0);

    // ---- gather1 chunks (main) overlapped with gemm2 chunks (s2) ----
    for (int c = 0; c < NCHUNKS; ++c) {
        const int n0 = c * crows;
        if (n0 >= n) { cudaEventRecord(evM2[c], 0); continue; }
        const int n1 = (n0 + crows < n) ? n0 + crows : n;
        const int nodes = n1 - n0;
        gather_kernel<128><<<(int)(((long long)nodes * 32 + 255) / 256), 256>>>(H1, A1, n0, n1);
        cudaEventRecord(evG1[c], 0);
        cudaStreamWaitEvent(s2, evG1[c], 0);
        const int blks = (nodes + 127) / 128;
        mma_gemm_kernel<64, true><<<dim3(blks, 1), 256, 0, s2>>>(
            A1 + (size_t)n0 * 128, Wf2, b1, H2 + (size_t)n0 * 64, nodes);
        cudaEventRecord(evM2[c], s2);
    }
    // gather2 needs ALL of H2
    for (int c = 0; c < NCHUNKS; ++c) cudaStreamWaitEvent(0, evM2[c], 0);

    // ---- gather2 chunks (main) overlapped with final chunks (s2) ----
    for (int c = 0; c < NCHUNKS; ++c) {
        const int n0 = c * crows;
        if (n0 >= n) continue;
        const int n1 = (n0 + crows < n) ? n0 + crows : n;
        const int nodes = n1 - n0;
        gather_kernel<64><<<(int)(((long long)nodes * 16 + 255) / 256), 256>>>(H2, A2, n0, n1);
        cudaEventRecord(evG2[c], 0);
        cudaStreamWaitEvent(s2, evG2[c], 0);
        final_kernel<<<(nodes + 255) / 256, 256, 0, s2>>>(A2, b2, Wf, bf, out, n0, n1);
    }
    // rejoin main so the harness's stream ordering sees all work complete
    cudaEventRecord(evJoin2, s2);
    cudaStreamWaitEvent(0, evJoin2, 0);
}

// round 14
// speedup vs baseline: 1.6832x; 1.6832x over previous
#include <cuda_runtime.h>
#include <cuda_bf16.h>
#include <stdint.h>
#include <math.h>

#define NN 100000
#define D1 128
#define D2 64
#define EMAX 4000000
#define SCAN_BLK 1024
#define MAXNB 128

typedef unsigned long long ull;

// ---------------- scratch (static __device__ — no runtime allocation) ----------------
__device__ float  g_dis[NN];
__device__ float2 g_dis2[NN];
__device__ int    g_deg[NN];
__device__ int    g_rowstart[NN];
__device__ int    g_cursor[NN];
__device__ int    g_csr[EMAX];
__device__ int    g_blocksum[MAXNB];
__device__ int    g_blockoff[MAXNB];
__device__ float  g_H1[(size_t)NN * D1];
__device__ float  g_A1[(size_t)NN * D1];
__device__ float  g_H2[(size_t)NN * D2];
__device__ float  g_A2[(size_t)NN * D2];
__device__ int    g_is64;
// W in mma-fragment order: per (col, kstep, tg) one uint4 {hi_b0, hi_b1, lo_b0, lo_b1}
__device__ uint32_t g_Wf1[128 * 8 * 4 * 4];   // 64KB
__device__ uint32_t g_Wf2[64 * 8 * 4 * 4];    // 32KB

// ---------------- f32x2 helpers (gathers) ----------------
__device__ __forceinline__ ull pack2(float lo, float hi) {
    ull r; asm("mov.b64 %0, {%1,%2};" : "=l"(r) : "f"(lo), "f"(hi)); return r;
}
__device__ __forceinline__ float2 unpack2(ull u) {
    float2 f; asm("mov.b64 {%0,%1}, %2;" : "=f"(f.x), "=f"(f.y) : "l"(u)); return f;
}
__device__ __forceinline__ void ffma2(ull& d, ull a, ull b, ull c) {
    asm("fma.rn.f32x2 %0, %1, %2, %3;" : "=l"(d) : "l"(a), "l"(b), "l"(c));
}
__device__ __forceinline__ void fmul2(ull& d, ull a, ull b) {
    asm("mul.rn.f32x2 %0, %1, %2;" : "=l"(d) : "l"(a), "l"(b));
}

__device__ __forceinline__ int load_idx(const void* ei, long long pos, int is64) {
    return is64 ? (int)((const long long*)ei)[pos] : ((const int*)ei)[pos];
}

__device__ __forceinline__ uint32_t pkb(__nv_bfloat16 a, __nv_bfloat16 b) {
    return (uint32_t)__bfloat16_as_ushort(a) | ((uint32_t)__bfloat16_as_ushort(b) << 16);
}

// split float2 -> bf16x2 hi word + bf16x2 lo word (residual)
__device__ __forceinline__ void split2(float2 v, uint32_t& h, uint32_t& l) {
    uint32_t hw;
    asm("cvt.rn.bf16x2.f32 %0, %1, %2;" : "=r"(hw) : "f"(v.y), "f"(v.x));
    const float hx = __uint_as_float(hw << 16);
    const float hy = __uint_as_float(hw & 0xffff0000u);
    const float lx = v.x - hx;
    const float ly = v.y - hy;
    uint32_t lw;
    asm("cvt.rn.bf16x2.f32 %0, %1, %2;" : "=r"(lw) : "f"(ly), "f"(lx));
    h = hw; l = lw;
}

__device__ __forceinline__ void mma16816(float* c, const uint32_t* a, uint32_t b0, uint32_t b1) {
    asm volatile(
        "mma.sync.aligned.m16n8k16.row.col.f32.bf16.bf16.f32 "
        "{%0,%1,%2,%3}, {%4,%5,%6,%7}, {%8,%9}, {%0,%1,%2,%3};"
        : "+f"(c[0]), "+f"(c[1]), "+f"(c[2]), "+f"(c[3])
        : "r"(a[0]), "r"(a[1]), "r"(a[2]), "r"(a[3]), "r"(b0), "r"(b1));
}

// ---------------- setup / CSR build ----------------
__global__ void setup_kernel(const unsigned int* ei, int n) {
    int i = blockIdx.x * blockDim.x + threadIdx.x;
    if (i < n) g_deg[i] = 0;
    if (blockIdx.x == 0) {
        __shared__ int any;
        if (threadIdx.x == 0) any = 0;
        __syncthreads();
        int local = 0;
        for (int j = threadIdx.x; j < 2048; j += blockDim.x)
            if (ei[2 * j + 1] != 0u) local = 1;
        if (local) any = 1;
        __syncthreads();
        if (threadIdx.x == 0) g_is64 = (any == 0) ? 1 : 0;
    }
}

__global__ void count_kernel(const void* __restrict__ ei, long long E) {
    long long e = (long long)blockIdx.x * blockDim.x + threadIdx.x;
    if (e >= E) return;
    int dst = load_idx(ei, E + e, g_is64);
    atomicAdd(&g_deg[dst], 1);
}

__global__ void scanA_kernel(int n) {
    __shared__ int s[SCAN_BLK];
    int i = blockIdx.x * SCAN_BLK + threadIdx.x;
    s[threadIdx.x] = (i < n) ? g_deg[i] : 0;
    __syncthreads();
    for (int off = SCAN_BLK / 2; off > 0; off >>= 1) {
        if (threadIdx.x < off) s[threadIdx.x] += s[threadIdx.x + off];
        __syncthreads();
    }
    if (threadIdx.x == 0) g_blocksum[blockIdx.x] = s[0];
}

__global__ void scanB_kernel(int nb) {
    __shared__ int s[MAXNB];
    int v = (threadIdx.x < nb) ? g_blocksum[threadIdx.x] : 0;
    s[threadIdx.x] = v;
    __syncthreads();
    for (int off = 1; off < MAXNB; off <<= 1) {
        int t = (threadIdx.x >= off) ? s[threadIdx.x - off] : 0;
        __syncthreads();
        s[threadIdx.x] += t;
        __syncthreads();
    }
    if (threadIdx.x < nb) g_blockoff[threadIdx.x] = s[threadIdx.x] - v;
}

__global__ void scanC_kernel(int n) {
    __shared__ int s[SCAN_BLK];
    int i = blockIdx.x * SCAN_BLK + threadIdx.x;
    int v = (i < n) ? g_deg[i] : 0;
    s[threadIdx.x] = v;
    __syncthreads();
    for (int off = 1; off < SCAN_BLK; off <<= 1) {
        int t = (threadIdx.x >= off) ? s[threadIdx.x - off] : 0;
        __syncthreads();
        s[threadIdx.x] += t;
        __syncthreads();
    }
    if (i < n) {
        int excl = s[threadIdx.x] - v + g_blockoff[blockIdx.x];
        g_rowstart[i] = excl;
        g_cursor[i] = excl;
        float d = rsqrtf((float)(v + 1));
        g_dis[i] = d;
        g_dis2[i] = make_float2(d, d);
    }
}

__global__ void fill_kernel(const void* __restrict__ ei, long long E) {
    long long e = (long long)blockIdx.x * blockDim.x + threadIdx.x;
    if (e >= E) return;
    const int is64 = g_is64;
    int src = load_idx(ei, e, is64);
    int dst = load_idx(ei, E + e, is64);
    int pos = atomicAdd(&g_cursor[dst], 1);
    g_csr[pos] = src;
}

// ---------------- weight prep: fragment-order bf16 hi/lo pack ----------------
__global__ void prep_w_kernel(const float* __restrict__ W1, const float* __restrict__ W2) {
    const int idx = blockIdx.x * blockDim.x + threadIdx.x;
    if (idx < 128 * 64) {
        const int c = idx >> 6, w = idx & 63;
        const int k = w * 2;
        const float x0 = W1[k * 128 + c], x1 = W1[(k + 1) * 128 + c];
        const __nv_bfloat16 h0 = __float2bfloat16_rn(x0), h1 = __float2bfloat16_rn(x1);
        const uint32_t hw = pkb(h0, h1);
        const uint32_t lw = pkb(__float2bfloat16_rn(x0 - __bfloat162float(h0)),
                                __float2bfloat16_rn(x1 - __bfloat162float(h1)));
        const int ks = w >> 3, wi = w & 7, tg = wi & 3, slot = wi >> 2;
        const int frag = (c * 8 + ks) * 4 + tg;
        g_Wf1[frag * 4 + slot] = hw;
        g_Wf1[frag * 4 + 2 + slot] = lw;
    }
    if (idx < 64 * 64) {
        const int c = idx >> 6, w = idx & 63;
        const int k = w * 2;
        const float x0 = W2[k * 64 + c], x1 = W2[(k + 1) * 64 + c];
        const __nv_bfloat16 h0 = __float2bfloat16_rn(x0), h1 = __float2bfloat16_rn(x1);
        const uint32_t hw = pkb(h0, h1);
        const uint32_t lw = pkb(__float2bfloat16_rn(x0 - __bfloat162float(h0)),
                                __float2bfloat16_rn(x1 - __bfloat162float(h1)));
        const int ks = w >> 3, wi = w & 7, tg = wi & 3, slot = wi >> 2;
        const int frag = (c * 8 + ks) * 4 + tg;
        g_Wf2[frag * 4 + slot] = hw;
        g_Wf2[frag * 4 + 2 + slot] = lw;
    }
}

// ---------------- HMMA GEMM: H = X@W, bf16 hi/lo split, fp32 accum -----------------
// IN=128. Block 256 thr = 8 warps; tile 128 rows x 64 cols; grid (rowb, OUT/64).
// A staged per 16-k chunk via smem (coalesced LDG.128, split once, LDS fragments).
// smem layout (dynamic): bs uint4[2048] (32KB) | 2 x { ash[1280], asl[1280] } (20KB)
#define A_STRIDE 10
template <int OUT, bool RELU_IN>
__global__ void __launch_bounds__(256)
mma_gemm_kernel(const float* __restrict__ X, const uint32_t* __restrict__ Wf,
                const float* __restrict__ bin, float* __restrict__ H, int n) {
    extern __shared__ char sm[];
    uint4* bs = (uint4*)sm;

    const int tid = threadIdx.x;
    const int lane = tid & 31;
    const int wid = tid >> 5;
    const int wr = wid >> 1;
    const int wc = wid & 1;
    const int g = lane >> 2;
    const int tg = lane & 3;
    const int row0 = blockIdx.x * 128;
    const int cb = blockIdx.y * 64;

    {
        const uint4* src = (const uint4*)Wf + cb * 32;
        #pragma unroll
        for (int i = tid; i < 2048; i += 256) bs[i] = src[i];
    }

    auto STAGE = [&](int ks, int b) {
        uint32_t* ah_s = (uint32_t*)(sm + 32768 + b * 10240);
        uint32_t* al_s = ah_s + 1280;
        #pragma unroll
        for (int p = 0; p < 2; ++p) {
            const int i = p * 256 + tid;        // 0..511
            const int r = i >> 2;
            const int q = i & 3;
            const int row = row0 + r;
            float4 v = make_float4(0.f, 0.f, 0.f, 0.f);
            if (row < n) {
                v = *(const float4*)&X[(size_t)row * 128 + ks * 16 + q * 4];
                if (RELU_IN) {
                    const float4 b4 = *(const float4*)&bin[ks * 16 + q * 4];
                    v.x = fmaxf(v.x + b4.x, 0.f);
                    v.y = fmaxf(v.y + b4.y, 0.f);
                    v.z = fmaxf(v.z + b4.z, 0.f);
                    v.w = fmaxf(v.w + b4.w, 0.f);
                }
            }
            uint32_t h0, l0, h1, l1;
            split2(make_float2(v.x, v.y), h0, l0);
            split2(make_float2(v.z, v.w), h1, l1);
            const int base = r * A_STRIDE + q * 2;
            ah_s[base] = h0; ah_s[base + 1] = h1;
            al_s[base] = l0; al_s[base + 1] = l1;
        }
    };

    float acc[2][4][4];
    #pragma unroll
    for (int mt = 0; mt < 2; ++mt)
        #pragma unroll
        for (int nt = 0; nt < 4; ++nt)
            #pragma unroll
            for (int q = 0; q < 4; ++q) acc[mt][nt][q] = 0.f;

    STAGE(0, 0);
    __syncthreads();

    #pragma unroll
    for (int ks = 0; ks < 8; ++ks) {
        if (ks < 7) STAGE(ks + 1, (ks + 1) & 1);

        const uint32_t* ah_s = (const uint32_t*)(sm + 32768 + (ks & 1) * 10240);
        const uint32_t* al_s = ah_s + 1280;

        uint32_t ah[2][4], al[2][4];
        #pragma unroll
        for (int mt = 0; mt < 2; ++mt) {
            const int lr0 = (wr * 32 + mt * 16 + g) * A_STRIDE;
            const int lr1 = lr0 + 8 * A_STRIDE;
            ah[mt][0] = ah_s[lr0 + tg];
            ah[mt][1] = ah_s[lr1 + tg];
            ah[mt][2] = ah_s[lr0 + tg + 4];
            ah[mt][3] = ah_s[lr1 + tg + 4];
            al[mt][0] = al_s[lr0 + tg];
            al[mt][1] = al_s[lr1 + tg];
            al[mt][2] = al_s[lr0 + tg + 4];
            al[mt][3] = al_s[lr1 + tg + 4];
        }
        uint32_t bh0[4], bh1[4], bl0[4], bl1[4];
        #pragma unroll
        for (int nt = 0; nt < 4; ++nt) {
            const int cl = wc * 32 + nt * 8 + g;
            const uint4 b = bs[(cl * 8 + ks) * 4 + tg];
            bh0[nt] = b.x; bh1[nt] = b.y; bl0[nt] = b.z; bl1[nt] = b.w;
        }
        #pragma unroll
        for (int mt = 0; mt < 2; ++mt)
            #pragma unroll
            for (int nt = 0; nt < 4; ++nt) {
                mma16816(acc[mt][nt], ah[mt], bh0[nt], bh1[nt]);
                mma16816(acc[mt][nt], ah[mt], bl0[nt], bl1[nt]);
                mma16816(acc[mt][nt], al[mt], bh0[nt], bh1[nt]);
            }
        __syncthreads();
    }

    #pragma unroll
    for (int mt = 0; mt < 2; ++mt) {
        const int r0 = row0 + wr * 32 + mt * 16 + g;
        const int r1 = r0 + 8;
        #pragma unroll
        for (int nt = 0; nt < 4; ++nt) {
            const int c0 = cb + wc * 32 + nt * 8 + tg * 2;
            if (r0 < n)
                *(float2*)&H[(size_t)r0 * OUT + c0] = make_float2(acc[mt][nt][0], acc[mt][nt][1]);
            if (r1 < n)
                *(float2*)&H[(size_t)r1 * OUT + c0] = make_float2(acc[mt][nt][2], acc[mt][nt][3]);
        }
    }
}

// -------- gather: A[d] = dis[d] * ( dis[d]*H[d] + sum_{s in N(d)} dis[s]*H[s] ) ------
template <int D>
__global__ void gather_kernel(const float* __restrict__ H, float* __restrict__ A, int n) {
    constexpr int LPN = D / 4;
    const long long gt = (long long)blockIdx.x * blockDim.x + threadIdx.x;
    const int node = (int)(gt / LPN);
    const int l = (int)(gt % LPN);
    if (node >= n) return;

    const float4* __restrict__ h4 = (const float4*)H;
    const ull* __restrict__ dis2 = (const ull*)g_dis2;
    const size_t col = (size_t)node * LPN + l;
    const ull dd = __ldg(&dis2[node]);

    float4 sv = h4[col];
    ull acc0, acc1;
    fmul2(acc0, pack2(sv.x, sv.y), dd);
    fmul2(acc1, pack2(sv.z, sv.w), dd);

    const int beg = g_rowstart[node];
    const int cnt = g_deg[node];

    #pragma unroll 4
    for (int j = 0; j < cnt; ++j) {
        const int src = __ldg(&g_csr[beg + j]);
        const ull ss = __ldg(&dis2[src]);
        const float4 v = h4[(size_t)src * LPN + l];
        ffma2(acc0, pack2(v.x, v.y), ss, acc0);
        ffma2(acc1, pack2(v.z, v.w), ss, acc1);
    }

    fmul2(acc0, acc0, dd);
    fmul2(acc1, acc1, dd);
    const float2 a = unpack2(acc0);
    const float2 b = unpack2(acc1);
    ((float4*)A)[col] = make_float4(a.x, a.y, b.x, b.y);
}

// ---------------- final: out = softmax(relu(A2+b2) @ Wf + bf) ----------------
__global__ void final_kernel(const float* __restrict__ A2, const float* __restrict__ b2,
                             const float* __restrict__ Wf, const float* __restrict__ bf,
                             float* __restrict__ out, int n) {
    __shared__ float Wfs[64 * 10];
    __shared__ float bfs[10];
    __shared__ float b2s[64];
    for (int i = threadIdx.x; i < 640; i += blockDim.x) Wfs[i] = Wf[i];
    if (threadIdx.x < 10) bfs[threadIdx.x] = bf[threadIdx.x];
    if (threadIdx.x < 64) b2s[threadIdx.x] = b2[threadIdx.x];
    __syncthreads();

    const int i = blockIdx.x * blockDim.x + threadIdx.x;
    if (i >= n) return;

    float acc[10];
    #pragma unroll
    for (int c = 0; c < 10; ++c) acc[c] = bfs[c];

    #pragma unroll
    for (int kk = 0; kk < 64; kk += 4) {
        float4 v = *(const float4*)&A2[(size_t)i * 64 + kk];
        v.x = fmaxf(v.x + b2s[kk + 0], 0.f);
        v.y = fmaxf(v.y + b2s[kk + 1], 0.f);
        v.z = fmaxf(v.z + b2s[kk + 2], 0.f);
        v.w = fmaxf(v.w + b2s[kk + 3], 0.f);
        #pragma unroll
        for (int c = 0; c < 10; ++c) {
            acc[c] = fmaf(v.x, Wfs[(kk + 0) * 10 + c], acc[c]);
            acc[c] = fmaf(v.y, Wfs[(kk + 1) * 10 + c], acc[c]);
            acc[c] = fmaf(v.z, Wfs[(kk + 2) * 10 + c], acc[c]);
            acc[c] = fmaf(v.w, Wfs[(kk + 3) * 10 + c], acc[c]);
        }
    }

    float m = acc[0];
    #pragma unroll
    for (int c = 1; c < 10; ++c) m = fmaxf(m, acc[c]);
    float s = 0.f;
    float ex[10];
    #pragma unroll
    for (int c = 0; c < 10; ++c) { ex[c] = expf(acc[c] - m); s += ex[c]; }
    const float inv = 1.0f / s;
    #pragma unroll
    for (int c = 0; c < 10; ++c) out[(size_t)i * 10 + c] = ex[c] * inv;
}

// ---------------- launch (R12 structure: CSR on side stream, single chain) ----------
extern "C" void kernel_launch(void* const* d_in, const int* in_sizes, int n_in,
                              void* d_out, int out_size) {
    const float* x  = (const float*)d_in[0];
    const void*  ei = d_in[1];
    const float* W1 = (const float*)d_in[2];
    const float* b1 = (const float*)d_in[3];
    const float* W2 = (const float*)d_in[4];
    const float* b2 = (const float*)d_in[5];
    const float* Wf = (const float*)d_in[6];
    const float* bf = (const float*)d_in[7];
    float* out = (float*)d_out;

    const long long E = (long long)in_sizes[1] / 2;
    const int n = in_sizes[0] / D1;
    const int nb = (n + SCAN_BLK - 1) / SCAN_BLK;

    float *H1, *A1, *H2, *A2;
    cudaGetSymbolAddress((void**)&H1, g_H1);
    cudaGetSymbolAddress((void**)&A1, g_A1);
    cudaGetSymbolAddress((void**)&H2, g_H2);
    cudaGetSymbolAddress((void**)&A2, g_A2);
    uint32_t *Wf1, *Wf2;
    cudaGetSymbolAddress((void**)&Wf1, g_Wf1);
    cudaGetSymbolAddress((void**)&Wf2, g_Wf2);

    const int smem_g = 32768 + 2 * 10240;   // 53248
    cudaFuncSetAttribute(mma_gemm_kernel<128, false>,
                         cudaFuncAttributeMaxDynamicSharedMemorySize, smem_g);
    cudaFuncSetAttribute(mma_gemm_kernel<64, true>,
                         cudaFuncAttributeMaxDynamicSharedMemorySize, smem_g);

    static cudaStream_t s1 = nullptr;
    static cudaEvent_t evFork = nullptr, evJoin = nullptr;
    if (!s1) {
        cudaStreamCreateWithFlags(&s1, cudaStreamNonBlocking);
        cudaEventCreateWithFlags(&evFork, cudaEventDisableTiming);
        cudaEventCreateWithFlags(&evJoin, cudaEventDisableTiming);
    }

    const int rowb = (n + 127) / 128;

    // main: prep(0) -> fork; CSR chain on s1; gemm1 at submission index 3 (ncu slot)
    prep_w_kernel<<<32, 256>>>(W1, W2);
    cudaEventRecord(evFork, 0);
    cudaStreamWaitEvent(s1, evFork, 0);
    setup_kernel<<<(n + 255) / 256, 256, 0, s1>>>((const unsigned int*)ei, n);
    if (E > 0) count_kernel<<<(int)((E + 255) / 256), 256, 0, s1>>>(ei, E);
    mma_gemm_kernel<128, false><<<dim3(rowb, 2), 256, smem_g>>>(x, Wf1, nullptr, H1, n);
    scanA_kernel<<<nb, SCAN_BLK, 0, s1>>>(n);
    scanB_kernel<<<1, MAXNB, 0, s1>>>(nb);
    scanC_kernel<<<nb, SCAN_BLK, 0, s1>>>(n);
    if (E > 0) fill_kernel<<<(int)((E + 255) / 256), 256, 0, s1>>>(ei, E);
    cudaEventRecord(evJoin, s1);

    // join: gather1 needs gemm1 (main) + CSR (side)
    cudaStreamWaitEvent(0, evJoin, 0);

    gather_kernel<128><<<(int)(((long long)n * 32 + 255) / 256), 256>>>(H1, A1, n);

    mma_gemm_kernel<64, true><<<dim3(rowb, 1), 256, smem_g>>>(A1, Wf2, b1, H2, n);
    gather_kernel<64><<<(int)(((long long)n * 16 + 255) / 256), 256>>>(H2, A2, n);

    final_kernel<<<(n + 255) / 256, 256>>>(A2, b2, Wf, bf, out, n);
}

// round 16
// speedup vs baseline: 1.7080x; 1.0148x over previous
#include <cuda_runtime.h>
#include <cuda_bf16.h>
#include <stdint.h>
#include <math.h>

#define NN 100000
#define D1 128
#define D2 64
#define EMAX 4000000
#define SCAN_BLK 1024
#define MAXNB 128

typedef unsigned long long ull;

// ---------------- scratch (static __device__ — no runtime allocation) ----------------
__device__ float  g_dis[NN];
__device__ float2 g_dis2[NN];
__device__ int    g_deg[NN];
__device__ int    g_rowstart[NN];
__device__ int    g_cursor[NN];
__device__ int    g_csr[EMAX];
__device__ int    g_blocksum[MAXNB];
__device__ int    g_blockoff[MAXNB];
__device__ float  g_H1[(size_t)NN * D1];
__device__ float  g_A1[(size_t)NN * D1];
__device__ float  g_H2[(size_t)NN * D2];
__device__ int    g_is64;
// W in mma-fragment order: per (col, kstep, tg) one uint4 {hi_b0, hi_b1, lo_b0, lo_b1}
__device__ uint32_t g_Wf1[128 * 8 * 4 * 4];   // 64KB
__device__ uint32_t g_Wf2[64 * 8 * 4 * 4];    // 32KB

// ---------------- f32x2 helpers (gathers) ----------------
__device__ __forceinline__ ull pack2(float lo, float hi) {
    ull r; asm("mov.b64 %0, {%1,%2};" : "=l"(r) : "f"(lo), "f"(hi)); return r;
}
__device__ __forceinline__ float2 unpack2(ull u) {
    float2 f; asm("mov.b64 {%0,%1}, %2;" : "=f"(f.x), "=f"(f.y) : "l"(u)); return f;
}
__device__ __forceinline__ void ffma2(ull& d, ull a, ull b, ull c) {
    asm("fma.rn.f32x2 %0, %1, %2, %3;" : "=l"(d) : "l"(a), "l"(b), "l"(c));
}
__device__ __forceinline__ void fmul2(ull& d, ull a, ull b) {
    asm("mul.rn.f32x2 %0, %1, %2;" : "=l"(d) : "l"(a), "l"(b));
}

__device__ __forceinline__ int load_idx(const void* ei, long long pos, int is64) {
    return is64 ? (int)((const long long*)ei)[pos] : ((const int*)ei)[pos];
}

__device__ __forceinline__ uint32_t pkb(__nv_bfloat16 a, __nv_bfloat16 b) {
    return (uint32_t)__bfloat16_as_ushort(a) | ((uint32_t)__bfloat16_as_ushort(b) << 16);
}

// split float2 -> bf16x2 hi word + bf16x2 lo word (residual)
__device__ __forceinline__ void split2(float2 v, uint32_t& h, uint32_t& l) {
    uint32_t hw;
    asm("cvt.rn.bf16x2.f32 %0, %1, %2;" : "=r"(hw) : "f"(v.y), "f"(v.x));
    const float hx = __uint_as_float(hw << 16);
    const float hy = __uint_as_float(hw & 0xffff0000u);
    const float lx = v.x - hx;
    const float ly = v.y - hy;
    uint32_t lw;
    asm("cvt.rn.bf16x2.f32 %0, %1, %2;" : "=r"(lw) : "f"(ly), "f"(lx));
    h = hw; l = lw;
}

__device__ __forceinline__ void mma16816(float* c, const uint32_t* a, uint32_t b0, uint32_t b1) {
    asm volatile(
        "mma.sync.aligned.m16n8k16.row.col.f32.bf16.bf16.f32 "
        "{%0,%1,%2,%3}, {%4,%5,%6,%7}, {%8,%9}, {%0,%1,%2,%3};"
        : "+f"(c[0]), "+f"(c[1]), "+f"(c[2]), "+f"(c[3])
        : "r"(a[0]), "r"(a[1]), "r"(a[2]), "r"(a[3]), "r"(b0), "r"(b1));
}

// ---------------- setup / CSR build ----------------
__global__ void setup_kernel(const unsigned int* ei, int n) {
    int i = blockIdx.x * blockDim.x + threadIdx.x;
    if (i < n) g_deg[i] = 0;
    if (blockIdx.x == 0) {
        __shared__ int any;
        if (threadIdx.x == 0) any = 0;
        __syncthreads();
        int local = 0;
        for (int j = threadIdx.x; j < 2048; j += blockDim.x)
            if (ei[2 * j + 1] != 0u) local = 1;
        if (local) any = 1;
        __syncthreads();
        if (threadIdx.x == 0) g_is64 = (any == 0) ? 1 : 0;
    }
}

__global__ void count_kernel(const void* __restrict__ ei, long long E) {
    long long e = (long long)blockIdx.x * blockDim.x + threadIdx.x;
    if (e >= E) return;
    int dst = load_idx(ei, E + e, g_is64);
    atomicAdd(&g_deg[dst], 1);
}

__global__ void scanA_kernel(int n) {
    __shared__ int s[SCAN_BLK];
    int i = blockIdx.x * SCAN_BLK + threadIdx.x;
    s[threadIdx.x] = (i < n) ? g_deg[i] : 0;
    __syncthreads();
    for (int off = SCAN_BLK / 2; off > 0; off >>= 1) {
        if (threadIdx.x < off) s[threadIdx.x] += s[threadIdx.x + off];
        __syncthreads();
    }
    if (threadIdx.x == 0) g_blocksum[blockIdx.x] = s[0];
}

__global__ void scanB_kernel(int nb) {
    __shared__ int s[MAXNB];
    int v = (threadIdx.x < nb) ? g_blocksum[threadIdx.x] : 0;
    s[threadIdx.x] = v;
    __syncthreads();
    for (int off = 1; off < MAXNB; off <<= 1) {
        int t = (threadIdx.x >= off) ? s[threadIdx.x - off] : 0;
        __syncthreads();
        s[threadIdx.x] += t;
        __syncthreads();
    }
    if (threadIdx.x < nb) g_blockoff[threadIdx.x] = s[threadIdx.x] - v;
}

__global__ void scanC_kernel(int n) {
    __shared__ int s[SCAN_BLK];
    int i = blockIdx.x * SCAN_BLK + threadIdx.x;
    int v = (i < n) ? g_deg[i] : 0;
    s[threadIdx.x] = v;
    __syncthreads();
    for (int off = 1; off < SCAN_BLK; off <<= 1) {
        int t = (threadIdx.x >= off) ? s[threadIdx.x - off] : 0;
        __syncthreads();
        s[threadIdx.x] += t;
        __syncthreads();
    }
    if (i < n) {
        int excl = s[threadIdx.x] - v + g_blockoff[blockIdx.x];
        g_rowstart[i] = excl;
        g_cursor[i] = excl;
        float d = rsqrtf((float)(v + 1));
        g_dis[i] = d;
        g_dis2[i] = make_float2(d, d);
    }
}

__global__ void fill_kernel(const void* __restrict__ ei, long long E) {
    long long e = (long long)blockIdx.x * blockDim.x + threadIdx.x;
    if (e >= E) return;
    const int is64 = g_is64;
    int src = load_idx(ei, e, is64);
    int dst = load_idx(ei, E + e, is64);
    int pos = atomicAdd(&g_cursor[dst], 1);
    g_csr[pos] = src;
}

// ---------------- weight prep: fragment-order bf16 hi/lo pack ----------------
__global__ void prep_w_kernel(const float* __restrict__ W1, const float* __restrict__ W2) {
    const int idx = blockIdx.x * blockDim.x + threadIdx.x;
    if (idx < 128 * 64) {
        const int c = idx >> 6, w = idx & 63;
        const int k = w * 2;
        const float x0 = W1[k * 128 + c], x1 = W1[(k + 1) * 128 + c];
        const __nv_bfloat16 h0 = __float2bfloat16_rn(x0), h1 = __float2bfloat16_rn(x1);
        const uint32_t hw = pkb(h0, h1);
        const uint32_t lw = pkb(__float2bfloat16_rn(x0 - __bfloat162float(h0)),
                                __float2bfloat16_rn(x1 - __bfloat162float(h1)));
        const int ks = w >> 3, wi = w & 7, tg = wi & 3, slot = wi >> 2;
        const int frag = (c * 8 + ks) * 4 + tg;
        g_Wf1[frag * 4 + slot] = hw;
        g_Wf1[frag * 4 + 2 + slot] = lw;
    }
    if (idx < 64 * 64) {
        const int c = idx >> 6, w = idx & 63;
        const int k = w * 2;
        const float x0 = W2[k * 64 + c], x1 = W2[(k + 1) * 64 + c];
        const __nv_bfloat16 h0 = __float2bfloat16_rn(x0), h1 = __float2bfloat16_rn(x1);
        const uint32_t hw = pkb(h0, h1);
        const uint32_t lw = pkb(__float2bfloat16_rn(x0 - __bfloat162float(h0)),
                                __float2bfloat16_rn(x1 - __bfloat162float(h1)));
        const int ks = w >> 3, wi = w & 7, tg = wi & 3, slot = wi >> 2;
        const int frag = (c * 8 + ks) * 4 + tg;
        g_Wf2[frag * 4 + slot] = hw;
        g_Wf2[frag * 4 + 2 + slot] = lw;
    }
}

// ---------------- HMMA GEMM: H = X@W, bf16 hi/lo split, fp32 accum -----------------
// IN=128. Block 256 thr = 8 warps; ONE block covers 128 rows x OUT cols.
// Warp (wr=wid>>1, wc=wid&1): rows wr*32..+31, cols wc*(OUT/2) + nt*8 (nt<OUT/16).
// A staged per 16-k chunk in FRAGMENT ORDER (pad-5): consumer reads uint4 per mt.
// smem: B frags (OUT*512 B) | 2 x { ah[320 u4], al[320 u4] } (20KB)
template <int OUT, bool RELU_IN>
__global__ void __launch_bounds__(256, 2)
mma_gemm_kernel(const float* __restrict__ X, const uint32_t* __restrict__ Wf,
                const float* __restrict__ bin, float* __restrict__ H, int n) {
    constexpr int NTW = OUT / 16;              // n-tiles per warp
    constexpr int B_U4 = OUT * 32;             // B frag uint4 count
    constexpr int SM_A = OUT * 512;            // byte offset of A buffers

    extern __shared__ char sm[];
    uint4* bs = (uint4*)sm;

    const int tid = threadIdx.x;
    const int lane = tid & 31;
    const int wid = tid >> 5;
    const int wr = wid >> 1;
    const int wc = wid & 1;
    const int g = lane >> 2;
    const int tg = lane & 3;
    const int row0 = blockIdx.x * 128;

    {
        const uint4* src = (const uint4*)Wf;
        #pragma unroll
        for (int i = tid; i < B_U4; i += 256) bs[i] = src[i];
    }

    auto STAGE = [&](int ks, int b) {
        uint32_t* ah_s = (uint32_t*)(sm + SM_A + b * 10240);
        uint32_t* al_s = ah_s + 1280;          // 320 uint4 = 5120B
        #pragma unroll
        for (int p = 0; p < 2; ++p) {
            const int i = p * 256 + tid;       // 0..511
            const int r = i >> 2;
            const int q = i & 3;
            const int row = row0 + r;
            float4 v = make_float4(0.f, 0.f, 0.f, 0.f);
            if (row < n) {
                v = *(const float4*)&X[(size_t)row * 128 + ks * 16 + q * 4];
                if (RELU_IN) {
                    const float4 b4 = *(const float4*)&bin[ks * 16 + q * 4];
                    v.x = fmaxf(v.x + b4.x, 0.f);
                    v.y = fmaxf(v.y + b4.y, 0.f);
                    v.z = fmaxf(v.z + b4.z, 0.f);
                    v.w = fmaxf(v.w + b4.w, 0.f);
                }
            }
            uint32_t h0, l0, h1, l1;
            split2(make_float2(v.x, v.y), h0, l0);   // k-pair 2q
            split2(make_float2(v.z, v.w), h1, l1);   // k-pair 2q+1
            const int rr = r & 15;
            const int gg = rr & 7;
            const int half = rr >> 3;
            const int rg = r >> 4;
            const int tg0 = (q & 1) * 2;
            const int comp = half + 2 * (q >> 1);
            const int base = ((rg * 8 + gg) * 5 + tg0) * 4 + comp;
            ah_s[base] = h0; ah_s[base + 4] = h1;
            al_s[base] = l0; al_s[base + 4] = l1;
        }
    };

    float acc[2][NTW][4];
    #pragma unroll
    for (int mt = 0; mt < 2; ++mt)
        #pragma unroll
        for (int nt = 0; nt < NTW; ++nt)
            #pragma unroll
            for (int q = 0; q < 4; ++q) acc[mt][nt][q] = 0.f;

    STAGE(0, 0);
    __syncthreads();

    #pragma unroll
    for (int ks = 0; ks < 8; ++ks) {
        if (ks < 7) STAGE(ks + 1, (ks + 1) & 1);

        const uint4* ahu = (const uint4*)(sm + SM_A + (ks & 1) * 10240);
        const uint4* alu = ahu + 320;

        uint32_t ah[2][4], al[2][4];
        #pragma unroll
        for (int mt = 0; mt < 2; ++mt) {
            const int rg = wr * 2 + mt;
            const uint4 a4 = ahu[(rg * 8 + g) * 5 + tg];
            ah[mt][0] = a4.x; ah[mt][1] = a4.y; ah[mt][2] = a4.z; ah[mt][3] = a4.w;
            const uint4 b4 = alu[(rg * 8 + g) * 5 + tg];
            al[mt][0] = b4.x; al[mt][1] = b4.y; al[mt][2] = b4.z; al[mt][3] = b4.w;
        }

        #pragma unroll
        for (int nt = 0; nt < NTW; ++nt) {
            const int c = wc * (OUT / 2) + nt * 8 + g;
            const uint4 b = bs[(c * 8 + ks) * 4 + tg];
            #pragma unroll
            for (int mt = 0; mt < 2; ++mt) {
                mma16816(acc[mt][nt], ah[mt], b.x, b.y);
                mma16816(acc[mt][nt], ah[mt], b.z, b.w);
                mma16816(acc[mt][nt], al[mt], b.x, b.y);
            }
        }
        __syncthreads();
    }

    #pragma unroll
    for (int mt = 0; mt < 2; ++mt) {
        const int r0 = row0 + wr * 32 + mt * 16 + g;
        const int r1 = r0 + 8;
        #pragma unroll
        for (int nt = 0; nt < NTW; ++nt) {
            const int c0 = wc * (OUT / 2) + nt * 8 + tg * 2;
            if (r0 < n)
                *(float2*)&H[(size_t)r0 * OUT + c0] = make_float2(acc[mt][nt][0], acc[mt][nt][1]);
            if (r1 < n)
                *(float2*)&H[(size_t)r1 * OUT + c0] = make_float2(acc[mt][nt][2], acc[mt][nt][3]);
        }
    }
}

// -------- gather1: A[d] = dis[d] * ( dis[d]*H[d] + sum_{s in N(d)} dis[s]*H[s] ) -----
template <int D>
__global__ void gather_kernel(const float* __restrict__ H, float* __restrict__ A, int n) {
    constexpr int LPN = D / 4;
    const long long gt = (long long)blockIdx.x * blockDim.x + threadIdx.x;
    const int node = (int)(gt / LPN);
    const int l = (int)(gt % LPN);
    if (node >= n) return;

    const float4* __restrict__ h4 = (const float4*)H;
    const ull* __restrict__ dis2 = (const ull*)g_dis2;
    const size_t col = (size_t)node * LPN + l;
    const ull dd = __ldg(&dis2[node]);

    float4 sv = h4[col];
    ull acc0, acc1;
    fmul2(acc0, pack2(sv.x, sv.y), dd);
    fmul2(acc1, pack2(sv.z, sv.w), dd);

    const int beg = g_rowstart[node];
    const int cnt = g_deg[node];

    #pragma unroll 4
    for (int j = 0; j < cnt; ++j) {
        const int src = __ldg(&g_csr[beg + j]);
        const ull ss = __ldg(&dis2[src]);
        const float4 v = h4[(size_t)src * LPN + l];
        ffma2(acc0, pack2(v.x, v.y), ss, acc0);
        ffma2(acc1, pack2(v.z, v.w), ss, acc1);
    }

    fmul2(acc0, acc0, dd);
    fmul2(acc1, acc1, dd);
    const float2 a = unpack2(acc0);
    const float2 b = unpack2(acc1);
    ((float4*)A)[col] = make_float4(a.x, a.y, b.x, b.y);
}

// ---- fused gather2+final: half-warp per node; logits via shfl reduce; softmax ----
__global__ void gf_kernel(const float* __restrict__ H2, const float* __restrict__ b2,
                          const float* __restrict__ Wf, const float* __restrict__ bf,
                          float* __restrict__ out, int n) {
    __shared__ float Wfs[64 * 10];
    __shared__ float bfs[10];
    __shared__ float b2s[64];
    for (int i = threadIdx.x; i < 640; i += blockDim.x) Wfs[i] = Wf[i];
    if (threadIdx.x < 10) bfs[threadIdx.x] = bf[threadIdx.x];
    if (threadIdx.x < 64) b2s[threadIdx.x] = b2[threadIdx.x];
    __syncthreads();

    const int lane = threadIdx.x & 31;
    const int wid = threadIdx.x >> 5;
    const int sl = lane & 15;               // lane within 16-group
    const int node = blockIdx.x * 16 + wid * 2 + (lane >> 4);
    const bool valid = node < n;
    const int nd = valid ? node : (n - 1);

    const float4* __restrict__ h4 = (const float4*)H2;
    const float d = g_dis[nd];

    // self term
    float4 a = h4[(size_t)nd * 16 + sl];
    float4 acc = make_float4(a.x * d, a.y * d, a.z * d, a.w * d);

    const int beg = g_rowstart[nd];
    const int cnt = g_deg[nd];
    for (int j = 0; j < cnt; ++j) {
        const int src = __ldg(&g_csr[beg + j]);
        const float s = __ldg(&g_dis[src]);
        const float4 v = h4[(size_t)src * 16 + sl];
        acc.x = fmaf(v.x, s, acc.x);
        acc.y = fmaf(v.y, s, acc.y);
        acc.z = fmaf(v.z, s, acc.z);
        acc.w = fmaf(v.w, s, acc.w);
    }

    // v = relu(d*acc + b2)
    const int k0 = sl * 4;
    float4 v;
    v.x = fmaxf(acc.x * d + b2s[k0 + 0], 0.f);
    v.y = fmaxf(acc.y * d + b2s[k0 + 1], 0.f);
    v.z = fmaxf(acc.z * d + b2s[k0 + 2], 0.f);
    v.w = fmaxf(acc.w * d + b2s[k0 + 3], 0.f);

    // partial logits over this lane's 4 dims
    float pl[10];
    #pragma unroll
    for (int c = 0; c < 10; ++c) {
        float t;
        t = v.x * Wfs[(k0 + 0) * 10 + c];
        t = fmaf(v.y, Wfs[(k0 + 1) * 10 + c], t);
        t = fmaf(v.z, Wfs[(k0 + 2) * 10 + c], t);
        t = fmaf(v.w, Wfs[(k0 + 3) * 10 + c], t);
        pl[c] = t;
    }

    // reduce across 16 lanes (both 16-groups in parallel, width=16)
    #pragma unroll
    for (int c = 0; c < 10; ++c) {
        #pragma unroll
        for (int off = 8; off > 0; off >>= 1)
            pl[c] += __shfl_down_sync(0xffffffffu, pl[c], off, 16);
    }

    if (valid && sl == 0) {
        float lg[10];
        #pragma unroll
        for (int c = 0; c < 10; ++c) lg[c] = pl[c] + bfs[c];
        float m = lg[0];
        #pragma unroll
        for (int c = 1; c < 10; ++c) m = fmaxf(m, lg[c]);
        float s = 0.f, ex[10];
        #pragma unroll
        for (int c = 0; c < 10; ++c) { ex[c] = expf(lg[c] - m); s += ex[c]; }
        const float inv = 1.0f / s;
        float* op = &out[(size_t)node * 10];
        #pragma unroll
        for (int c = 0; c < 10; c += 2)
            *(float2*)(op + c) = make_float2(ex[c] * inv, ex[c + 1] * inv);
    }
}

// ---------------- launch (CSR on side stream, single main chain) ----------
extern "C" void kernel_launch(void* const* d_in, const int* in_sizes, int n_in,
                              void* d_out, int out_size) {
    const float* x  = (const float*)d_in[0];
    const void*  ei = d_in[1];
    const float* W1 = (const float*)d_in[2];
    const float* b1 = (const float*)d_in[3];
    const float* W2 = (const float*)d_in[4];
    const float* b2 = (const float*)d_in[5];
    const float* Wf = (const float*)d_in[6];
    const float* bf = (const float*)d_in[7];
    float* out = (float*)d_out;

    const long long E = (long long)in_sizes[1] / 2;
    const int n = in_sizes[0] / D1;
    const int nb = (n + SCAN_BLK - 1) / SCAN_BLK;

    float *H1, *A1, *H2;
    cudaGetSymbolAddress((void**)&H1, g_H1);
    cudaGetSymbolAddress((void**)&A1, g_A1);
    cudaGetSymbolAddress((void**)&H2, g_H2);
    uint32_t *Wf1, *Wf2;
    cudaGetSymbolAddress((void**)&Wf1, g_Wf1);
    cudaGetSymbolAddress((void**)&Wf2, g_Wf2);

    const int smem1 = 128 * 512 + 2 * 10240;   // 86016 (OUT=128)
    const int smem2 = 64 * 512 + 2 * 10240;    // 53248 (OUT=64)
    cudaFuncSetAttribute(mma_gemm_kernel<128, false>,
                         cudaFuncAttributeMaxDynamicSharedMemorySize, smem1);
    cudaFuncSetAttribute(mma_gemm_kernel<64, true>,
                         cudaFuncAttributeMaxDynamicSharedMemorySize, smem2);

    static cudaStream_t s1 = nullptr;
    static cudaEvent_t evFork = nullptr, evJoin = nullptr;
    if (!s1) {
        cudaStreamCreateWithFlags(&s1, cudaStreamNonBlocking);
        cudaEventCreateWithFlags(&evFork, cudaEventDisableTiming);
        cudaEventCreateWithFlags(&evJoin, cudaEventDisableTiming);
    }

    const int rowb = (n + 127) / 128;

    // main: prep(0) -> fork; CSR chain on s1; gemm1 at submission index 3 (ncu slot)
    prep_w_kernel<<<32, 256>>>(W1, W2);
    cudaEventRecord(evFork, 0);
    cudaStreamWaitEvent(s1, evFork, 0);
    setup_kernel<<<(n + 255) / 256, 256, 0, s1>>>((const unsigned int*)ei, n);
    if (E > 0) count_kernel<<<(int)((E + 255) / 256), 256, 0, s1>>>(ei, E);
    mma_gemm_kernel<128, false><<<rowb, 256, smem1>>>(x, Wf1, nullptr, H1, n);
    scanA_kernel<<<nb, SCAN_BLK, 0, s1>>>(n);
    scanB_kernel<<<1, MAXNB, 0, s1>>>(nb);
    scanC_kernel<<<nb, SCAN_BLK, 0, s1>>>(n);
    if (E > 0) fill_kernel<<<(int)((E + 255) / 256), 256, 0, s1>>>(ei, E);
    cudaEventRecord(evJoin, s1);

    // join: gather1 needs gemm1 (main) + CSR (side)
    cudaStreamWaitEvent(0, evJoin, 0);

    gather_kernel<128><<<(int)(((long long)n * 32 + 255) / 256), 256>>>(H1, A1, n);

    mma_gemm_kernel<64, true><<<rowb, 256, smem2>>>(A1, Wf2, b1, H2, n);

    gf_kernel<<<(n + 15) / 16, 256>>>(H2, b2, Wf, bf, out, n);
}